// round 15
// baseline (speedup 1.0000x reference)
#include <cuda_runtime.h>
#include <cuda_bf16.h>
#include <cstdint>

// Problem constants
constexpr int B  = 4;
constexpr int T  = 1024;
constexpr int E  = 1024;
constexpr int H  = 16;
constexpr int DH = 64;
constexpr int M  = B * T;        // 4096
constexpr int HD = H * DH;       // 1024
constexpr int N3 = 3 * HD;       // 3072

// Pre-split bf16 operand arrays (hi/lo decomposition)
__device__ __nv_bfloat16 g_xh[M * E],  g_xl[M * E];     // x            [m][k]
__device__ __nv_bfloat16 g_Wh[E * N3], g_Wl[E * N3];    // Wq|Wk|Wv     [k][n]
__device__ __nv_bfloat16 g_Woh[E * HD], g_Wol[E * HD];  // Wo           [n][k]
__device__ __nv_bfloat16 g_Qh[B * H * T * DH], g_Ql[B * H * T * DH];   // [b][h][t][d]
__device__ __nv_bfloat16 g_Kh[B * H * T * DH], g_Kl[B * H * T * DH];
__device__ __nv_bfloat16 g_Vh[B * H * T * DH], g_Vl[B * H * T * DH];
__device__ __nv_bfloat16 g_Oh[M * HD], g_Ol[M * HD];    // attn out     [m][k]

// ---------------------------------------------------------------------------
// helpers
// ---------------------------------------------------------------------------
__device__ __forceinline__ uint32_t smem_u32(const void* p) {
    uint32_t a;
    asm("{ .reg .u64 t; cvta.to.shared.u64 t, %1; cvt.u32.u64 %0, t; }" : "=r"(a) : "l"(p));
    return a;
}
__device__ __forceinline__ void cp16(uint32_t dst, const void* src) {
    asm volatile("cp.async.cg.shared.global [%0], [%1], 16;" :: "r"(dst), "l"(src));
}
#define CP_COMMIT() asm volatile("cp.async.commit_group;" ::: "memory")
#define CP_WAIT0()  asm volatile("cp.async.wait_group 0;" ::: "memory")

__device__ __forceinline__ void ldsm_x4(uint32_t& r0, uint32_t& r1, uint32_t& r2, uint32_t& r3,
                                        uint32_t addr) {
    asm volatile("ldmatrix.sync.aligned.m8n8.x4.shared.b16 {%0,%1,%2,%3}, [%4];"
                 : "=r"(r0), "=r"(r1), "=r"(r2), "=r"(r3) : "r"(addr));
}
__device__ __forceinline__ void ldsm_x2(uint32_t& r0, uint32_t& r1, uint32_t addr) {
    asm volatile("ldmatrix.sync.aligned.m8n8.x2.shared.b16 {%0,%1}, [%2];"
                 : "=r"(r0), "=r"(r1) : "r"(addr));
}
__device__ __forceinline__ void ldsm_x2_t(uint32_t& r0, uint32_t& r1, uint32_t addr) {
    asm volatile("ldmatrix.sync.aligned.m8n8.x2.trans.shared.b16 {%0,%1}, [%2];"
                 : "=r"(r0), "=r"(r1) : "r"(addr));
}
__device__ __forceinline__ void mma_bf16(float* c, const uint32_t* a, const uint32_t* b) {
    asm volatile(
        "mma.sync.aligned.m16n8k16.row.col.f32.bf16.bf16.f32 "
        "{%0,%1,%2,%3}, {%4,%5,%6,%7}, {%8,%9}, {%0,%1,%2,%3};"
        : "+f"(c[0]), "+f"(c[1]), "+f"(c[2]), "+f"(c[3])
        : "r"(a[0]), "r"(a[1]), "r"(a[2]), "r"(a[3]), "r"(b[0]), "r"(b[1]));
}
__device__ __forceinline__ void split2(float a, float b, uint32_t& hi, uint32_t& lo) {
    __nv_bfloat16 ha = __float2bfloat16(a), hb = __float2bfloat16(b);
    __nv_bfloat16 la = __float2bfloat16(a - __bfloat162float(ha));
    __nv_bfloat16 lb = __float2bfloat16(b - __bfloat162float(hb));
    hi = (uint32_t)__bfloat16_as_ushort(ha) | ((uint32_t)__bfloat16_as_ushort(hb) << 16);
    lo = (uint32_t)__bfloat16_as_ushort(la) | ((uint32_t)__bfloat16_as_ushort(lb) << 16);
}

// GEMM tiling: CTA tile 128x64, warp grid 4x2 (warp tile 32x32), 3 CTAs/SM
constexpr int BK   = 32;
constexpr int NK   = 32;
constexpr int PK   = 40;                   // [row][k] padded k-stride (bf16)
constexpr int PKN2 = 72;                   // [k][n] padded n-stride (bf16), 64-wide tiles
constexpr int A_BYTES  = 128 * PK * 2;     // 10240 per hi/lo array
constexpr int B_SLOT   = 64 * PK * 2;      // 5120 (covers both B layouts; [k][n] uses 4608)
constexpr int BUF_BYTES = 2 * A_BYTES + 2 * B_SLOT;   // 30720
constexpr int GEMM_SMEM = 2 * BUF_BYTES;   // 61440

// ---------------------------------------------------------------------------
// Merged prepass: fp32 -> hi/lo bf16 splits (x, Wq|Wk|Wv, Wo) in one kernel
// ---------------------------------------------------------------------------
__global__ void conv_all(const float* __restrict__ x,
                         const float* __restrict__ Wq,
                         const float* __restrict__ Wk,
                         const float* __restrict__ Wv,
                         const float* __restrict__ Wo) {
    int b = blockIdx.x;
    uint32_t h01, l01, h23, l23;
    if (b < 4096) {                          // x: 1M float4
        int flat = b * 256 + threadIdx.x;
        float4 v = *(const float4*)(x + (size_t)flat * 4);
        split2(v.x, v.y, h01, l01);
        split2(v.z, v.w, h23, l23);
        ((uint2*)g_xh)[flat] = make_uint2(h01, h23);
        ((uint2*)g_xl)[flat] = make_uint2(l01, l23);
    } else if (b < 7168) {                   // W -> [k][n]
        int bx  = b - 4096;
        int sel = bx >> 10;
        const float* Wsel = (sel == 0) ? Wq : (sel == 1) ? Wk : Wv;
        int flat = (bx & 1023) * 256 + threadIdx.x;
        int h = flat >> 14, rem = flat & 16383;
        int e = rem >> 4, d4 = rem & 15;
        float4 v = *(const float4*)(Wsel + ((size_t)(h * E + e)) * DH + d4 * 4);
        split2(v.x, v.y, h01, l01);
        split2(v.z, v.w, h23, l23);
        size_t idx = (size_t)e * N3 + sel * HD + h * DH + d4 * 4;
        *(uint2*)(g_Wh + idx) = make_uint2(h01, h23);
        *(uint2*)(g_Wl + idx) = make_uint2(l01, l23);
    } else {                                 // Wo [n][k]
        int flat = (b - 7168) * 256 + threadIdx.x;
        float4 v = *(const float4*)(Wo + (size_t)flat * 4);
        split2(v.x, v.y, h01, l01);
        split2(v.z, v.w, h23, l23);
        ((uint2*)g_Woh)[flat] = make_uint2(h01, h23);
        ((uint2*)g_Wol)[flat] = make_uint2(l01, l23);
    }
}

// ---------------------------------------------------------------------------
// cp.async tile loaders
// ---------------------------------------------------------------------------
// A: 128 rows x 32 k from [row][k] gmem -> PK-padded hi/lo pair at buffer base
__device__ __forceinline__ void cpA128(const __nv_bfloat16* srcH, const __nv_bfloat16* srcL,
                                       int ld, int row0, int k0, uint32_t base, int tid) {
    #pragma unroll
    for (int j = 0; j < 2; j++) {
        int flat = j * 256 + tid;
        int r = flat >> 2, c4 = (flat & 3) * 8;
        size_t s = (size_t)(row0 + r) * ld + k0 + c4;
        uint32_t d = base + (uint32_t)(r * PK + c4) * 2;
        cp16(d, srcH + s);
        cp16(d + A_BYTES, srcL + s);
    }
}
// B [k][n]: 32 k-rows x 64 n from g_W -> PKN2-padded hi/lo pair (qkv)
__device__ __forceinline__ void cpB_kn64(int ncol0, int k0, uint32_t base, int tid) {
    int kr = tid >> 3, nc = (tid & 7) * 8;
    size_t s = (size_t)(k0 + kr) * N3 + ncol0 + nc;
    uint32_t d = base + 2 * A_BYTES + (uint32_t)(kr * PKN2 + nc) * 2;
    cp16(d, g_Wh + s);
    cp16(d + B_SLOT, g_Wl + s);
}
// B [n][k]: 64 rows x 32 k from g_Wo -> PK-padded hi/lo pair (outproj)
__device__ __forceinline__ void cpB_nk64(int n0, int k0, uint32_t base, int tid) {
    int r = tid >> 2, c4 = (tid & 3) * 8;
    size_t s = (size_t)(n0 + r) * HD + k0 + c4;
    uint32_t d = base + 2 * A_BYTES + (uint32_t)(r * PK + c4) * 2;
    cp16(d, g_Woh + s);
    cp16(d + B_SLOT, g_Wol + s);
}

// ---------------------------------------------------------------------------
// Compute core: 128x64 CTA tile, warp grid 4(wy) x 2(wx), warp tile 32x32.
// BT = true: B [k][n] (PKN2) via ldsm.x2.trans; false: B [n][k] (PK) via ldsm.x2
// ---------------------------------------------------------------------------
template <bool BT>
__device__ __forceinline__ void gemm64(uint32_t base, float c[2][4][4],
                                       int lane, int wy, int wx) {
    const uint32_t aH = base;
    const uint32_t aL = base + A_BYTES;
    const uint32_t bH = base + 2 * A_BYTES;
    const uint32_t bL = bH + B_SLOT;
    const int arow  = wy * 32 + (lane & 15);
    const int acol8 = (lane >> 4) * 8;

    #pragma unroll
    for (int ks = 0; ks < 2; ks++) {
        const int k0 = ks * 16;
        uint32_t Bh[4][2], Bl[4][2];
        if (BT) {
            const int krow = k0 + (lane & 15);
            #pragma unroll
            for (int ni = 0; ni < 4; ni++) {
                uint32_t off = (uint32_t)(krow * PKN2 + wx * 32 + ni * 8) * 2;
                ldsm_x2_t(Bh[ni][0], Bh[ni][1], bH + off);
                ldsm_x2_t(Bl[ni][0], Bl[ni][1], bL + off);
            }
        } else {
            const int brow  = wx * 32 + (lane & 7);
            const int bcol8 = ((lane >> 3) & 1) * 8;
            #pragma unroll
            for (int ni = 0; ni < 4; ni++) {
                uint32_t off = (uint32_t)((brow + ni * 8) * PK + k0 + bcol8) * 2;
                ldsm_x2(Bh[ni][0], Bh[ni][1], bH + off);
                ldsm_x2(Bl[ni][0], Bl[ni][1], bL + off);
            }
        }
        #pragma unroll
        for (int mi = 0; mi < 2; mi++) {
            uint32_t Ah[4], Al[4];
            uint32_t off = (uint32_t)((arow + mi * 16) * PK + k0 + acol8) * 2;
            ldsm_x4(Ah[0], Ah[1], Ah[2], Ah[3], aH + off);
            ldsm_x4(Al[0], Al[1], Al[2], Al[3], aL + off);
            #pragma unroll
            for (int ni = 0; ni < 4; ni++) mma_bf16(c[mi][ni], Ah, Bh[ni]);
            #pragma unroll
            for (int ni = 0; ni < 4; ni++) mma_bf16(c[mi][ni], Ah, Bl[ni]);
            #pragma unroll
            for (int ni = 0; ni < 4; ni++) mma_bf16(c[mi][ni], Al, Bh[ni]);
        }
    }
}

// ---------------------------------------------------------------------------
// Kernel 1: QKV projection — 128x64 tiles, 3 CTAs/SM, cp.async pipeline
// ---------------------------------------------------------------------------
__global__ void __launch_bounds__(256, 3)
qkv_mma()
{
    extern __shared__ char smbuf[];
    const uint32_t sb0 = smem_u32(smbuf);
    const int tid  = threadIdx.x;
    const int lane = tid & 31;
    const int wid  = tid >> 5;
    const int wy = wid >> 1, wx = wid & 1;

    const int m0    = blockIdx.x * 128;
    const int nblk  = blockIdx.y;                 // 0..47 (64-wide)
    const int ncol0 = nblk * 64;                  // col in concatenated [k][3072]
    const int sel   = nblk >> 4;
    const int hh    = nblk & 15;                  // head within projection
    __nv_bfloat16* OutH = (sel == 0) ? g_Qh : (sel == 1) ? g_Kh : g_Vh;
    __nv_bfloat16* OutL = (sel == 0) ? g_Ql : (sel == 1) ? g_Kl : g_Vl;

    float c[2][4][4] = {};

    cpA128(g_xh, g_xl, E, m0, 0, sb0, tid);
    cpB_kn64(ncol0, 0, sb0, tid);
    CP_COMMIT(); CP_WAIT0();
    __syncthreads();

    for (int kt = 0; kt < NK; kt++) {
        uint32_t buf  = sb0 + (kt & 1) * BUF_BYTES;
        uint32_t nbuf = sb0 + ((kt + 1) & 1) * BUF_BYTES;
        if (kt + 1 < NK) {
            cpA128(g_xh, g_xl, E, m0, (kt + 1) * BK, nbuf, tid);
            cpB_kn64(ncol0, (kt + 1) * BK, nbuf, tid);
            CP_COMMIT();
        }
        gemm64<true>(buf, c, lane, wy, wx);
        if (kt + 1 < NK) CP_WAIT0();
        __syncthreads();
    }

    // Epilogue: split accumulators, write bf16 hi/lo [b][h][t][d]
    const int g = lane >> 2, tg = lane & 3;
    #pragma unroll
    for (int mi = 0; mi < 2; mi++) {
        #pragma unroll
        for (int half = 0; half < 2; half++) {
            int m  = m0 + wy * 32 + mi * 16 + g + half * 8;
            int bb = m >> 10, t = m & 1023;
            #pragma unroll
            for (int ni = 0; ni < 4; ni++) {
                int d = wx * 32 + ni * 8 + tg * 2;
                uint32_t hi, lo;
                split2(c[mi][ni][half * 2], c[mi][ni][half * 2 + 1], hi, lo);
                size_t idx = ((size_t)((bb * H + hh) * T + t)) * DH + d;
                *(uint32_t*)(OutH + idx) = hi;
                *(uint32_t*)(OutL + idx) = lo;
            }
        }
    }
}

// ---------------------------------------------------------------------------
// Kernel 3: output projection — 128x64 tiles, 3 CTAs/SM.  out = O*Wo^T + bo
// ---------------------------------------------------------------------------
__global__ void __launch_bounds__(256, 3)
outproj_mma(const float* __restrict__ bo, float* __restrict__ out)
{
    extern __shared__ char smbuf[];
    const uint32_t sb0 = smem_u32(smbuf);
    const int tid  = threadIdx.x;
    const int lane = tid & 31;
    const int wid  = tid >> 5;
    const int wy = wid >> 1, wx = wid & 1;

    const int m0 = blockIdx.x * 128;
    const int n0 = blockIdx.y * 64;

    float c[2][4][4] = {};

    cpA128(g_Oh, g_Ol, HD, m0, 0, sb0, tid);
    cpB_nk64(n0, 0, sb0, tid);
    CP_COMMIT(); CP_WAIT0();
    __syncthreads();

    for (int kt = 0; kt < NK; kt++) {
        uint32_t buf  = sb0 + (kt & 1) * BUF_BYTES;
        uint32_t nbuf = sb0 + ((kt + 1) & 1) * BUF_BYTES;
        if (kt + 1 < NK) {
            cpA128(g_Oh, g_Ol, HD, m0, (kt + 1) * BK, nbuf, tid);
            cpB_nk64(n0, (kt + 1) * BK, nbuf, tid);
            CP_COMMIT();
        }
        gemm64<false>(buf, c, lane, wy, wx);
        if (kt + 1 < NK) CP_WAIT0();
        __syncthreads();
    }

    const int g = lane >> 2, tg = lane & 3;
    #pragma unroll
    for (int mi = 0; mi < 2; mi++) {
        #pragma unroll
        for (int half = 0; half < 2; half++) {
            int m = m0 + wy * 32 + mi * 16 + g + half * 8;
            #pragma unroll
            for (int ni = 0; ni < 4; ni++) {
                int n = n0 + wx * 32 + ni * 8 + tg * 2;
                float2 bv = *(const float2*)(bo + n);
                float2 val = make_float2(c[mi][ni][half * 2] + bv.x,
                                         c[mi][ni][half * 2 + 1] + bv.y);
                *(float2*)(out + (size_t)m * E + n) = val;
            }
        }
    }
}

// ---------------------------------------------------------------------------
// Kernel 2: causal flash attention — unchanged from round-12 pass
// ---------------------------------------------------------------------------
constexpr int PKA = 72;
constexpr int QREG   = 128 * PKA * 2;           // 18432 per Q array
constexpr int KSTR   = 64 * PKA * 2;            // 9216 per K/V array
constexpr int STAGEB = 4 * KSTR;                // 36864 per stage
constexpr int ATTN_SMEM = 2 * QREG + 2 * STAGEB;   // 110592

__device__ __forceinline__ void cpKV(uint32_t dst, size_t gbase, int tid) {
    #pragma unroll
    for (int j = 0; j < 2; j++) {
        int flat = j * 256 + tid;
        int r = flat >> 3, c8 = (flat & 7) * 8;
        size_t s = gbase + r * DH + c8;
        uint32_t d = dst + (uint32_t)(r * PKA + c8) * 2;
        cp16(d,            g_Kh + s);
        cp16(d + KSTR,     g_Kl + s);
        cp16(d + 2 * KSTR, g_Vh + s);
        cp16(d + 3 * KSTR, g_Vl + s);
    }
}

__global__ void __launch_bounds__(256, 2)
attn_mma()
{
    extern __shared__ char sm[];
    const uint32_t sb = smem_u32(sm);
    __nv_bfloat16* Qh = (__nv_bfloat16*)sm;
    __nv_bfloat16* Ql = Qh + 128 * PKA;
    const uint32_t stage0 = sb + 2 * QREG;

    const int tid = threadIdx.x, lane = tid & 31, w = tid >> 5;
    const int g = lane >> 2, tg = lane & 3;
    const int qb  = 7 - blockIdx.x;
    const int bh  = blockIdx.y;
    const int qr0 = qb * 128;
    const int rw0 = qr0 + w * 16;
    const size_t bhT = (size_t)bh * T;

    cpKV(stage0, (bhT + 0) * DH, tid);
    CP_COMMIT();
    {
        const __nv_bfloat16* QgH = g_Qh + (bhT + qr0) * DH;
        const __nv_bfloat16* QgL = g_Ql + (bhT + qr0) * DH;
        #pragma unroll
        for (int j = 0; j < 4; j++) {
            int flat = j * 256 + tid;
            int r = flat >> 3, c8 = (flat & 7) * 8;
            *(uint4*)(Qh + r * PKA + c8) = *(const uint4*)(QgH + r * DH + c8);
            *(uint4*)(Ql + r * PKA + c8) = *(const uint4*)(QgL + r * DH + c8);
        }
    }

    const uint32_t aQh = sb, aQl = sb + QREG;

    float O[8][4] = {};
    float mrow[2] = {-1e30f, -1e30f};
    float lrow[2] = {0.f, 0.f};
    const float scale = 0.125f;

    const int jbmax = 2 * qb + 1;
    for (int jb = 0; jb <= jbmax; jb++) {
        CP_WAIT0();
        __syncthreads();
        if (jb < jbmax) {
            cpKV(stage0 + ((jb + 1) & 1) * STAGEB, (bhT + (jb + 1) * 64) * DH, tid);
            CP_COMMIT();
        }
        const uint32_t aKh = stage0 + (jb & 1) * STAGEB;
        const uint32_t aKl = aKh + KSTR;
        const uint32_t aVh = aKh + 2 * KSTR;
        const uint32_t aVl = aKh + 3 * KSTR;

        if (jb * 64 > rw0 + 15) continue;

        float c[8][4] = {};
        #pragma unroll
        for (int ks = 0; ks < 4; ks++) {
            uint32_t Ah[4], Al[4];
            uint32_t offA = (uint32_t)((w * 16 + (lane & 15)) * PKA + ks * 16 + (lane >> 4) * 8) * 2;
            ldsm_x4(Ah[0], Ah[1], Ah[2], Ah[3], aQh + offA);
            ldsm_x4(Al[0], Al[1], Al[2], Al[3], aQl + offA);
            #pragma unroll
            for (int nj = 0; nj < 4; nj++) {
                const int n0i = 2 * nj, n1i = 2 * nj + 1;
                uint32_t B0h[2], B0l[2], B1h[2], B1l[2];
                uint32_t ob0 = (uint32_t)((n0i * 8 + (lane & 7)) * PKA + ks * 16 + ((lane >> 3) & 1) * 8) * 2;
                uint32_t ob1 = (uint32_t)((n1i * 8 + (lane & 7)) * PKA + ks * 16 + ((lane >> 3) & 1) * 8) * 2;
                ldsm_x2(B0h[0], B0h[1], aKh + ob0);
                ldsm_x2(B0l[0], B0l[1], aKl + ob0);
                ldsm_x2(B1h[0], B1h[1], aKh + ob1);
                ldsm_x2(B1l[0], B1l[1], aKl + ob1);
                mma_bf16(c[n0i], Ah, B0h);  mma_bf16(c[n1i], Ah, B1h);
                mma_bf16(c[n0i], Ah, B0l);  mma_bf16(c[n1i], Ah, B1l);
                mma_bf16(c[n0i], Al, B0h);  mma_bf16(c[n1i], Al, B1h);
            }
        }

        if (jb * 64 + 63 > rw0) {
            #pragma unroll
            for (int ni = 0; ni < 8; ni++) {
                int sgb = jb * 64 + ni * 8 + tg * 2;
                #pragma unroll
                for (int e = 0; e < 4; e++) {
                    int sg = sgb + (e & 1);
                    int rg = rw0 + g + ((e >> 1) << 3);
                    if (sg > rg) c[ni][e] = -1e30f;
                }
            }
        }

        float tm0 = -1e30f, tm1 = -1e30f;
        #pragma unroll
        for (int ni = 0; ni < 8; ni++) {
            tm0 = fmaxf(tm0, fmaxf(c[ni][0], c[ni][1]));
            tm1 = fmaxf(tm1, fmaxf(c[ni][2], c[ni][3]));
        }
        tm0 *= scale; tm1 *= scale;
        #pragma unroll
        for (int off = 1; off <= 2; off <<= 1) {
            tm0 = fmaxf(tm0, __shfl_xor_sync(0xffffffffu, tm0, off));
            tm1 = fmaxf(tm1, __shfl_xor_sync(0xffffffffu, tm1, off));
        }
        float mn0 = fmaxf(mrow[0], tm0), mn1 = fmaxf(mrow[1], tm1);
        float al0 = __expf(mrow[0] - mn0), al1 = __expf(mrow[1] - mn1);
        float rs0 = 0.f, rs1 = 0.f;
        #pragma unroll
        for (int ni = 0; ni < 8; ni++) {
            c[ni][0] = __expf(fmaf(scale, c[ni][0], -mn0));
            c[ni][1] = __expf(fmaf(scale, c[ni][1], -mn0));
            c[ni][2] = __expf(fmaf(scale, c[ni][2], -mn1));
            c[ni][3] = __expf(fmaf(scale, c[ni][3], -mn1));
            rs0 += c[ni][0] + c[ni][1];
            rs1 += c[ni][2] + c[ni][3];
        }
        #pragma unroll
        for (int off = 1; off <= 2; off <<= 1) {
            rs0 += __shfl_xor_sync(0xffffffffu, rs0, off);
            rs1 += __shfl_xor_sync(0xffffffffu, rs1, off);
        }
        lrow[0] = lrow[0] * al0 + rs0;
        lrow[1] = lrow[1] * al1 + rs1;
        mrow[0] = mn0; mrow[1] = mn1;
        #pragma unroll
        for (int ni = 0; ni < 8; ni++) {
            O[ni][0] *= al0; O[ni][1] *= al0;
            O[ni][2] *= al1; O[ni][3] *= al1;
        }

        #pragma unroll
        for (int ks = 0; ks < 4; ks++) {
            uint32_t Ph[4], Pl[4];
            split2(c[2 * ks][0],     c[2 * ks][1],     Ph[0], Pl[0]);
            split2(c[2 * ks][2],     c[2 * ks][3],     Ph[1], Pl[1]);
            split2(c[2 * ks + 1][0], c[2 * ks + 1][1], Ph[2], Pl[2]);
            split2(c[2 * ks + 1][2], c[2 * ks + 1][3], Ph[3], Pl[3]);
            #pragma unroll
            for (int nj = 0; nj < 4; nj++) {
                const int n0i = 2 * nj, n1i = 2 * nj + 1;
                uint32_t B0h[2], B0l[2], B1h[2], B1l[2];
                uint32_t ov0 = (uint32_t)((ks * 16 + (lane & 15)) * PKA + n0i * 8) * 2;
                uint32_t ov1 = (uint32_t)((ks * 16 + (lane & 15)) * PKA + n1i * 8) * 2;
                ldsm_x2_t(B0h[0], B0h[1], aVh + ov0);
                ldsm_x2_t(B0l[0], B0l[1], aVl + ov0);
                ldsm_x2_t(B1h[0], B1h[1], aVh + ov1);
                ldsm_x2_t(B1l[0], B1l[1], aVl + ov1);
                mma_bf16(O[n0i], Ph, B0h);  mma_bf16(O[n1i], Ph, B1h);
                mma_bf16(O[n0i], Ph, B0l);  mma_bf16(O[n1i], Ph, B1l);
                mma_bf16(O[n0i], Pl, B0h);  mma_bf16(O[n1i], Pl, B1h);
            }
        }
    }

    const float inv0 = 1.0f / lrow[0], inv1 = 1.0f / lrow[1];
    const int b = bh >> 4, h = bh & 15;
    const int t0 = rw0 + g, t1 = t0 + 8;
    #pragma unroll
    for (int ni = 0; ni < 8; ni++) {
        int col = h * DH + ni * 8 + tg * 2;
        uint32_t hi, lo;
        split2(O[ni][0] * inv0, O[ni][1] * inv0, hi, lo);
        size_t i0 = (size_t)(b * T + t0) * HD + col;
        *(uint32_t*)(g_Oh + i0) = hi;
        *(uint32_t*)(g_Ol + i0) = lo;
        split2(O[ni][2] * inv1, O[ni][3] * inv1, hi, lo);
        size_t i1 = (size_t)(b * T + t1) * HD + col;
        *(uint32_t*)(g_Oh + i1) = hi;
        *(uint32_t*)(g_Ol + i1) = lo;
    }
}

// ---------------------------------------------------------------------------
extern "C" void kernel_launch(void* const* d_in, const int* in_sizes, int n_in,
                              void* d_out, int out_size)
{
    const float* x  = (const float*)d_in[0];
    const float* Wq = (const float*)d_in[1];
    const float* Wk = (const float*)d_in[2];
    const float* Wv = (const float*)d_in[3];
    const float* Wo = (const float*)d_in[4];
    const float* bo = (const float*)d_in[5];
    float* out = (float*)d_out;
    (void)in_sizes; (void)n_in; (void)out_size;

    cudaFuncSetAttribute(qkv_mma,     cudaFuncAttributeMaxDynamicSharedMemorySize, GEMM_SMEM);
    cudaFuncSetAttribute(outproj_mma, cudaFuncAttributeMaxDynamicSharedMemorySize, GEMM_SMEM);
    cudaFuncSetAttribute(attn_mma,    cudaFuncAttributeMaxDynamicSharedMemorySize, ATTN_SMEM);

    conv_all<<<8192, 256>>>(x, Wq, Wk, Wv, Wo);
    qkv_mma<<<dim3(M / 128, 48), 256, GEMM_SMEM>>>();
    attn_mma<<<dim3(T / 128, B * H), 256, ATTN_SMEM>>>();
    outproj_mma<<<dim3(M / 128, 16), 256, GEMM_SMEM>>>(bo, out);
}

// round 16
// speedup vs baseline: 1.4377x; 1.4377x over previous
#include <cuda_runtime.h>
#include <cuda_fp16.h>
#include <cstdint>

// Problem constants
constexpr int B  = 4;
constexpr int T  = 1024;
constexpr int E  = 1024;
constexpr int H  = 16;
constexpr int DH = 64;
constexpr int M  = B * T;        // 4096
constexpr int HD = H * DH;       // 1024
constexpr int N3 = 3 * HD;       // 3072

// fp16 operand arrays. A-side operands carry hi/lo split; B-side single fp16.
__device__ __half g_xh[M * E],  g_xl[M * E];    // x        [m][k]  (A, split)
__device__ __half g_W1[E * N3];                 // Wq|Wk|Wv [k][n]  (B, single)
__device__ __half g_Wo1[E * HD];                // Wo       [n][k]  (B, single)
__device__ __half g_Qh[B * H * T * DH], g_Ql[B * H * T * DH];  // Q (A, split)
__device__ __half g_K1[B * H * T * DH];         // K (B, single)
__device__ __half g_V1[B * H * T * DH];         // V (B, single)
__device__ __half g_Oh[M * HD], g_Ol[M * HD];   // attn out [m][k] (A, split)

// ---------------------------------------------------------------------------
// helpers
// ---------------------------------------------------------------------------
__device__ __forceinline__ uint32_t smem_u32(const void* p) {
    uint32_t a;
    asm("{ .reg .u64 t; cvta.to.shared.u64 t, %1; cvt.u32.u64 %0, t; }" : "=r"(a) : "l"(p));
    return a;
}
__device__ __forceinline__ void cp16(uint32_t dst, const void* src) {
    asm volatile("cp.async.cg.shared.global [%0], [%1], 16;" :: "r"(dst), "l"(src));
}
#define CP_COMMIT() asm volatile("cp.async.commit_group;" ::: "memory")
#define CP_WAIT0()  asm volatile("cp.async.wait_group 0;" ::: "memory")

__device__ __forceinline__ void ldsm_x4(uint32_t& r0, uint32_t& r1, uint32_t& r2, uint32_t& r3,
                                        uint32_t addr) {
    asm volatile("ldmatrix.sync.aligned.m8n8.x4.shared.b16 {%0,%1,%2,%3}, [%4];"
                 : "=r"(r0), "=r"(r1), "=r"(r2), "=r"(r3) : "r"(addr));
}
__device__ __forceinline__ void ldsm_x2(uint32_t& r0, uint32_t& r1, uint32_t addr) {
    asm volatile("ldmatrix.sync.aligned.m8n8.x2.shared.b16 {%0,%1}, [%2];"
                 : "=r"(r0), "=r"(r1) : "r"(addr));
}
__device__ __forceinline__ void ldsm_x2_t(uint32_t& r0, uint32_t& r1, uint32_t addr) {
    asm volatile("ldmatrix.sync.aligned.m8n8.x2.trans.shared.b16 {%0,%1}, [%2];"
                 : "=r"(r0), "=r"(r1) : "r"(addr));
}
__device__ __forceinline__ void mma_f16(float* c, const uint32_t* a, const uint32_t* b) {
    asm volatile(
        "mma.sync.aligned.m16n8k16.row.col.f32.f16.f16.f32 "
        "{%0,%1,%2,%3}, {%4,%5,%6,%7}, {%8,%9}, {%0,%1,%2,%3};"
        : "+f"(c[0]), "+f"(c[1]), "+f"(c[2]), "+f"(c[3])
        : "r"(a[0]), "r"(a[1]), "r"(a[2]), "r"(a[3]), "r"(b[0]), "r"(b[1]));
}
// fp16 hi/lo split of two floats -> packed u32s
__device__ __forceinline__ void split2h(float a, float b, uint32_t& hi, uint32_t& lo) {
    __half ha = __float2half_rn(a), hb = __float2half_rn(b);
    __half la = __float2half_rn(a - __half2float(ha));
    __half lb = __float2half_rn(b - __half2float(hb));
    hi = (uint32_t)__half_as_ushort(ha) | ((uint32_t)__half_as_ushort(hb) << 16);
    lo = (uint32_t)__half_as_ushort(la) | ((uint32_t)__half_as_ushort(lb) << 16);
}
__device__ __forceinline__ uint32_t pack2h(float a, float b) {
    __half2 h = __floats2half2_rn(a, b);
    return *(uint32_t*)&h;
}

// GEMM tiling: CTA tile 128x128, warp grid 2x4 (warp tile 64x32), 2 CTAs/SM
constexpr int BK  = 32;
constexpr int NK  = 32;
constexpr int PK  = 40;                   // [row][k] padded k-stride (halves)
constexpr int PKN = 136;                  // [k][n] padded n-stride (halves)
constexpr int A_BYTES  = 128 * PK * 2;    // 10240 per A array (hi or lo)
constexpr int B_BYTES  = 128 * PK * 2;    // 10240 slot (covers [k][n] 8704 too)
constexpr int BUF_BYTES = 2 * A_BYTES + B_BYTES;   // 30720
constexpr int GEMM_SMEM = 2 * BUF_BYTES;  // 61440

// ---------------------------------------------------------------------------
// Merged prepass: fp32 -> fp16 (x split; W, Wo single) in one kernel
// ---------------------------------------------------------------------------
__global__ void conv_all(const float* __restrict__ x,
                         const float* __restrict__ Wq,
                         const float* __restrict__ Wk,
                         const float* __restrict__ Wv,
                         const float* __restrict__ Wo) {
    int b = blockIdx.x;
    if (b < 4096) {                          // x: split hi/lo
        int flat = b * 256 + threadIdx.x;
        float4 v = *(const float4*)(x + (size_t)flat * 4);
        uint32_t h01, l01, h23, l23;
        split2h(v.x, v.y, h01, l01);
        split2h(v.z, v.w, h23, l23);
        ((uint2*)g_xh)[flat] = make_uint2(h01, h23);
        ((uint2*)g_xl)[flat] = make_uint2(l01, l23);
    } else if (b < 7168) {                   // W -> [k][n], single fp16
        int bx  = b - 4096;
        int sel = bx >> 10;
        const float* Wsel = (sel == 0) ? Wq : (sel == 1) ? Wk : Wv;
        int flat = (bx & 1023) * 256 + threadIdx.x;
        int h = flat >> 14, rem = flat & 16383;
        int e = rem >> 4, d4 = rem & 15;
        float4 v = *(const float4*)(Wsel + ((size_t)(h * E + e)) * DH + d4 * 4);
        size_t idx = (size_t)e * N3 + sel * HD + h * DH + d4 * 4;
        *(uint2*)(g_W1 + idx) = make_uint2(pack2h(v.x, v.y), pack2h(v.z, v.w));
    } else {                                 // Wo [n][k], single fp16
        int flat = (b - 7168) * 256 + threadIdx.x;
        float4 v = *(const float4*)(Wo + (size_t)flat * 4);
        ((uint2*)g_Wo1)[flat] = make_uint2(pack2h(v.x, v.y), pack2h(v.z, v.w));
    }
}

// ---------------------------------------------------------------------------
// cp.async tile loaders
// ---------------------------------------------------------------------------
// A split pair: 128 rows x 32 k from [row][k] gmem
__device__ __forceinline__ void cpA(const __half* srcH, const __half* srcL,
                                    int ld, int row0, int k0, uint32_t base, int tid) {
    #pragma unroll
    for (int j = 0; j < 2; j++) {
        int flat = j * 256 + tid;
        int r = flat >> 2, c4 = (flat & 3) * 8;
        size_t s = (size_t)(row0 + r) * ld + k0 + c4;
        uint32_t d = base + (uint32_t)(r * PK + c4) * 2;
        cp16(d, srcH + s);
        cp16(d + A_BYTES, srcL + s);
    }
}
// B single [k][n]: 32 k-rows x 128 n from g_W1 (qkv)
__device__ __forceinline__ void cpB_kn(int ncol0, int k0, uint32_t base, int tid) {
    #pragma unroll
    for (int j = 0; j < 2; j++) {
        int flat = j * 256 + tid;
        int kr = flat >> 4, nc = (flat & 15) * 8;
        size_t s = (size_t)(k0 + kr) * N3 + ncol0 + nc;
        cp16(base + 2 * A_BYTES + (uint32_t)(kr * PKN + nc) * 2, g_W1 + s);
    }
}
// B single [n][k]: 128 rows x 32 k from g_Wo1 (outproj)
__device__ __forceinline__ void cpB_nk(int n0, int k0, uint32_t base, int tid) {
    #pragma unroll
    for (int j = 0; j < 2; j++) {
        int flat = j * 256 + tid;
        int r = flat >> 2, c4 = (flat & 3) * 8;
        size_t s = (size_t)(n0 + r) * HD + k0 + c4;
        cp16(base + 2 * A_BYTES + (uint32_t)(r * PK + c4) * 2, g_Wo1 + s);
    }
}

// ---------------------------------------------------------------------------
// Compute core — 2-term asymmetric split: c += Ah*B; c += Al*B
// BT = true: B [k][n] (PKN) via ldsm.x2.trans; false: B [n][k] (PK) via ldsm.x2
// ---------------------------------------------------------------------------
template <bool BT>
__device__ __forceinline__ void gemm_compute(uint32_t base, float c[4][4][4],
                                             int lane, int wy, int wx) {
    const uint32_t aH = base;
    const uint32_t aL = base + A_BYTES;
    const uint32_t bB = base + 2 * A_BYTES;
    const int arow  = wy * 64 + (lane & 15);
    const int acol8 = (lane >> 4) * 8;

    #pragma unroll
    for (int ks = 0; ks < 2; ks++) {
        const int k0 = ks * 16;
        uint32_t Bf[4][2];
        if (BT) {
            const int krow = k0 + (lane & 15);
            #pragma unroll
            for (int ni = 0; ni < 4; ni++) {
                uint32_t off = (uint32_t)(krow * PKN + wx * 32 + ni * 8) * 2;
                ldsm_x2_t(Bf[ni][0], Bf[ni][1], bB + off);
            }
        } else {
            const int brow  = wx * 32 + (lane & 7);
            const int bcol8 = ((lane >> 3) & 1) * 8;
            #pragma unroll
            for (int ni = 0; ni < 4; ni++) {
                uint32_t off = (uint32_t)((brow + ni * 8) * PK + k0 + bcol8) * 2;
                ldsm_x2(Bf[ni][0], Bf[ni][1], bB + off);
            }
        }
        #pragma unroll
        for (int mi = 0; mi < 4; mi++) {
            uint32_t Ah[4], Al[4];
            uint32_t off = (uint32_t)((arow + mi * 16) * PK + k0 + acol8) * 2;
            ldsm_x4(Ah[0], Ah[1], Ah[2], Ah[3], aH + off);
            ldsm_x4(Al[0], Al[1], Al[2], Al[3], aL + off);
            #pragma unroll
            for (int ni = 0; ni < 4; ni++) mma_f16(c[mi][ni], Ah, Bf[ni]);
            #pragma unroll
            for (int ni = 0; ni < 4; ni++) mma_f16(c[mi][ni], Al, Bf[ni]);
        }
    }
}

// ---------------------------------------------------------------------------
// Kernel 1: QKV projection — cp.async double-buffered pipeline
// ---------------------------------------------------------------------------
__global__ void __launch_bounds__(256, 2)
qkv_mma()
{
    extern __shared__ char smbuf[];
    const uint32_t sb0 = smem_u32(smbuf);
    const int tid  = threadIdx.x;
    const int lane = tid & 31;
    const int wid  = tid >> 5;
    const int wy = wid >> 2, wx = wid & 3;

    const int m0    = blockIdx.x * 128;
    const int nblk  = blockIdx.y;
    const int ncol0 = nblk * 128;
    const int sel   = nblk >> 3;
    const int nn0   = (nblk & 7) * 128;

    float c[4][4][4] = {};

    cpA(g_xh, g_xl, E, m0, 0, sb0, tid);
    cpB_kn(ncol0, 0, sb0, tid);
    CP_COMMIT(); CP_WAIT0();
    __syncthreads();

    for (int kt = 0; kt < NK; kt++) {
        uint32_t buf  = sb0 + (kt & 1) * BUF_BYTES;
        uint32_t nbuf = sb0 + ((kt + 1) & 1) * BUF_BYTES;
        if (kt + 1 < NK) {
            cpA(g_xh, g_xl, E, m0, (kt + 1) * BK, nbuf, tid);
            cpB_kn(ncol0, (kt + 1) * BK, nbuf, tid);
            CP_COMMIT();
        }
        gemm_compute<true>(buf, c, lane, wy, wx);
        if (kt + 1 < NK) CP_WAIT0();
        __syncthreads();
    }

    // Epilogue: Q written split fp16; K/V written single fp16.  [b][h][t][d]
    const int g = lane >> 2, tg = lane & 3;
    #pragma unroll
    for (int mi = 0; mi < 4; mi++) {
        #pragma unroll
        for (int half = 0; half < 2; half++) {
            int m  = m0 + wy * 64 + mi * 16 + g + half * 8;
            int bb = m >> 10, t = m & 1023;
            #pragma unroll
            for (int ni = 0; ni < 4; ni++) {
                int n = nn0 + wx * 32 + ni * 8 + tg * 2;
                int h = n >> 6, d = n & 63;
                size_t idx = ((size_t)((bb * H + h) * T + t)) * DH + d;
                float v0 = c[mi][ni][half * 2], v1 = c[mi][ni][half * 2 + 1];
                if (sel == 0) {
                    uint32_t hi, lo;
                    split2h(v0, v1, hi, lo);
                    *(uint32_t*)(g_Qh + idx) = hi;
                    *(uint32_t*)(g_Ql + idx) = lo;
                } else {
                    __half* Out = (sel == 1) ? g_K1 : g_V1;
                    *(uint32_t*)(Out + idx) = pack2h(v0, v1);
                }
            }
        }
    }
}

// ---------------------------------------------------------------------------
// Kernel 3: output projection.  out = O*Wo^T + bo
// ---------------------------------------------------------------------------
__global__ void __launch_bounds__(256, 2)
outproj_mma(const float* __restrict__ bo, float* __restrict__ out)
{
    extern __shared__ char smbuf[];
    const uint32_t sb0 = smem_u32(smbuf);
    const int tid  = threadIdx.x;
    const int lane = tid & 31;
    const int wid  = tid >> 5;
    const int wy = wid >> 2, wx = wid & 3;

    const int m0 = blockIdx.x * 128;
    const int n0 = blockIdx.y * 128;

    float c[4][4][4] = {};

    cpA(g_Oh, g_Ol, HD, m0, 0, sb0, tid);
    cpB_nk(n0, 0, sb0, tid);
    CP_COMMIT(); CP_WAIT0();
    __syncthreads();

    for (int kt = 0; kt < NK; kt++) {
        uint32_t buf  = sb0 + (kt & 1) * BUF_BYTES;
        uint32_t nbuf = sb0 + ((kt + 1) & 1) * BUF_BYTES;
        if (kt + 1 < NK) {
            cpA(g_Oh, g_Ol, HD, m0, (kt + 1) * BK, nbuf, tid);
            cpB_nk(n0, (kt + 1) * BK, nbuf, tid);
            CP_COMMIT();
        }
        gemm_compute<false>(buf, c, lane, wy, wx);
        if (kt + 1 < NK) CP_WAIT0();
        __syncthreads();
    }

    const int g = lane >> 2, tg = lane & 3;
    #pragma unroll
    for (int mi = 0; mi < 4; mi++) {
        #pragma unroll
        for (int half = 0; half < 2; half++) {
            int m = m0 + wy * 64 + mi * 16 + g + half * 8;
            #pragma unroll
            for (int ni = 0; ni < 4; ni++) {
                int n = n0 + wx * 32 + ni * 8 + tg * 2;
                float2 bv = *(const float2*)(bo + n);
                float2 val = make_float2(c[mi][ni][half * 2] + bv.x,
                                         c[mi][ni][half * 2 + 1] + bv.y);
                *(float2*)(out + (size_t)m * E + n) = val;
            }
        }
    }
}

// ---------------------------------------------------------------------------
// Kernel 2: causal flash attention — Q split fp16, K/V single fp16
// ---------------------------------------------------------------------------
constexpr int PKA = 72;
constexpr int QREG   = 128 * PKA * 2;           // 18432 per Q array
constexpr int KSTR   = 64 * PKA * 2;            // 9216 per K/V array
constexpr int STAGEB = 2 * KSTR;                // 18432 per stage (K1, V1)
constexpr int ATTN_SMEM = 2 * QREG + 2 * STAGEB;   // 73728

__device__ __forceinline__ void cpKV(uint32_t dst, size_t gbase, int tid) {
    #pragma unroll
    for (int j = 0; j < 2; j++) {
        int flat = j * 256 + tid;
        int r = flat >> 3, c8 = (flat & 7) * 8;
        size_t s = gbase + r * DH + c8;
        uint32_t d = dst + (uint32_t)(r * PKA + c8) * 2;
        cp16(d,        g_K1 + s);
        cp16(d + KSTR, g_V1 + s);
    }
}

__global__ void __launch_bounds__(256, 2)
attn_mma()
{
    extern __shared__ char sm[];
    const uint32_t sb = smem_u32(sm);
    __half* Qh = (__half*)sm;
    __half* Ql = Qh + 128 * PKA;
    const uint32_t stage0 = sb + 2 * QREG;

    const int tid = threadIdx.x, lane = tid & 31, w = tid >> 5;
    const int g = lane >> 2, tg = lane & 3;
    const int qb  = 7 - blockIdx.x;
    const int bh  = blockIdx.y;
    const int qr0 = qb * 128;
    const int rw0 = qr0 + w * 16;
    const size_t bhT = (size_t)bh * T;

    cpKV(stage0, (bhT + 0) * DH, tid);
    CP_COMMIT();
    {
        const __half* QgH = g_Qh + (bhT + qr0) * DH;
        const __half* QgL = g_Ql + (bhT + qr0) * DH;
        #pragma unroll
        for (int j = 0; j < 4; j++) {
            int flat = j * 256 + tid;
            int r = flat >> 3, c8 = (flat & 7) * 8;
            *(uint4*)(Qh + r * PKA + c8) = *(const uint4*)(QgH + r * DH + c8);
            *(uint4*)(Ql + r * PKA + c8) = *(const uint4*)(QgL + r * DH + c8);
        }
    }

    const uint32_t aQh = sb, aQl = sb + QREG;

    float O[8][4] = {};
    float mrow[2] = {-1e30f, -1e30f};
    float lrow[2] = {0.f, 0.f};
    const float scale = 0.125f;

    const int jbmax = 2 * qb + 1;
    for (int jb = 0; jb <= jbmax; jb++) {
        CP_WAIT0();
        __syncthreads();
        if (jb < jbmax) {
            cpKV(stage0 + ((jb + 1) & 1) * STAGEB, (bhT + (jb + 1) * 64) * DH, tid);
            CP_COMMIT();
        }
        const uint32_t aK = stage0 + (jb & 1) * STAGEB;
        const uint32_t aV = aK + KSTR;

        if (jb * 64 > rw0 + 15) continue;

        // ---- S = Q * K^T, 2-term split, ni-pair interleaved ----
        float c[8][4] = {};
        #pragma unroll
        for (int ks = 0; ks < 4; ks++) {
            uint32_t Ah[4], Al[4];
            uint32_t offA = (uint32_t)((w * 16 + (lane & 15)) * PKA + ks * 16 + (lane >> 4) * 8) * 2;
            ldsm_x4(Ah[0], Ah[1], Ah[2], Ah[3], aQh + offA);
            ldsm_x4(Al[0], Al[1], Al[2], Al[3], aQl + offA);
            #pragma unroll
            for (int nj = 0; nj < 4; nj++) {
                const int n0i = 2 * nj, n1i = 2 * nj + 1;
                uint32_t B0[2], B1[2];
                uint32_t ob0 = (uint32_t)((n0i * 8 + (lane & 7)) * PKA + ks * 16 + ((lane >> 3) & 1) * 8) * 2;
                uint32_t ob1 = (uint32_t)((n1i * 8 + (lane & 7)) * PKA + ks * 16 + ((lane >> 3) & 1) * 8) * 2;
                ldsm_x2(B0[0], B0[1], aK + ob0);
                ldsm_x2(B1[0], B1[1], aK + ob1);
                mma_f16(c[n0i], Ah, B0);  mma_f16(c[n1i], Ah, B1);
                mma_f16(c[n0i], Al, B0);  mma_f16(c[n1i], Al, B1);
            }
        }

        if (jb * 64 + 63 > rw0) {
            #pragma unroll
            for (int ni = 0; ni < 8; ni++) {
                int sgb = jb * 64 + ni * 8 + tg * 2;
                #pragma unroll
                for (int e = 0; e < 4; e++) {
                    int sg = sgb + (e & 1);
                    int rg = rw0 + g + ((e >> 1) << 3);
                    if (sg > rg) c[ni][e] = -1e30f;
                }
            }
        }

        float tm0 = -1e30f, tm1 = -1e30f;
        #pragma unroll
        for (int ni = 0; ni < 8; ni++) {
            tm0 = fmaxf(tm0, fmaxf(c[ni][0], c[ni][1]));
            tm1 = fmaxf(tm1, fmaxf(c[ni][2], c[ni][3]));
        }
        tm0 *= scale; tm1 *= scale;
        #pragma unroll
        for (int off = 1; off <= 2; off <<= 1) {
            tm0 = fmaxf(tm0, __shfl_xor_sync(0xffffffffu, tm0, off));
            tm1 = fmaxf(tm1, __shfl_xor_sync(0xffffffffu, tm1, off));
        }
        float mn0 = fmaxf(mrow[0], tm0), mn1 = fmaxf(mrow[1], tm1);
        float al0 = __expf(mrow[0] - mn0), al1 = __expf(mrow[1] - mn1);
        float rs0 = 0.f, rs1 = 0.f;
        #pragma unroll
        for (int ni = 0; ni < 8; ni++) {
            c[ni][0] = __expf(fmaf(scale, c[ni][0], -mn0));
            c[ni][1] = __expf(fmaf(scale, c[ni][1], -mn0));
            c[ni][2] = __expf(fmaf(scale, c[ni][2], -mn1));
            c[ni][3] = __expf(fmaf(scale, c[ni][3], -mn1));
            rs0 += c[ni][0] + c[ni][1];
            rs1 += c[ni][2] + c[ni][3];
        }
        #pragma unroll
        for (int off = 1; off <= 2; off <<= 1) {
            rs0 += __shfl_xor_sync(0xffffffffu, rs0, off);
            rs1 += __shfl_xor_sync(0xffffffffu, rs1, off);
        }
        lrow[0] = lrow[0] * al0 + rs0;
        lrow[1] = lrow[1] * al1 + rs1;
        mrow[0] = mn0; mrow[1] = mn1;
        #pragma unroll
        for (int ni = 0; ni < 8; ni++) {
            O[ni][0] *= al0; O[ni][1] *= al0;
            O[ni][2] *= al1; O[ni][3] *= al1;
        }

        // ---- O += P * V, P split fp16 in regs, V single ----
        #pragma unroll
        for (int ks = 0; ks < 4; ks++) {
            uint32_t Ph[4], Pl[4];
            split2h(c[2 * ks][0],     c[2 * ks][1],     Ph[0], Pl[0]);
            split2h(c[2 * ks][2],     c[2 * ks][3],     Ph[1], Pl[1]);
            split2h(c[2 * ks + 1][0], c[2 * ks + 1][1], Ph[2], Pl[2]);
            split2h(c[2 * ks + 1][2], c[2 * ks + 1][3], Ph[3], Pl[3]);
            #pragma unroll
            for (int nj = 0; nj < 4; nj++) {
                const int n0i = 2 * nj, n1i = 2 * nj + 1;
                uint32_t B0[2], B1[2];
                uint32_t ov0 = (uint32_t)((ks * 16 + (lane & 15)) * PKA + n0i * 8) * 2;
                uint32_t ov1 = (uint32_t)((ks * 16 + (lane & 15)) * PKA + n1i * 8) * 2;
                ldsm_x2_t(B0[0], B0[1], aV + ov0);
                ldsm_x2_t(B1[0], B1[1], aV + ov1);
                mma_f16(O[n0i], Ph, B0);  mma_f16(O[n1i], Ph, B1);
                mma_f16(O[n0i], Pl, B0);  mma_f16(O[n1i], Pl, B1);
            }
        }
    }

    // epilogue: normalize + split fp16, write [m][h*DH+d]
    const float inv0 = 1.0f / lrow[0], inv1 = 1.0f / lrow[1];
    const int b = bh >> 4, h = bh & 15;
    const int t0 = rw0 + g, t1 = t0 + 8;
    #pragma unroll
    for (int ni = 0; ni < 8; ni++) {
        int col = h * DH + ni * 8 + tg * 2;
        uint32_t hi, lo;
        split2h(O[ni][0] * inv0, O[ni][1] * inv0, hi, lo);
        size_t i0 = (size_t)(b * T + t0) * HD + col;
        *(uint32_t*)(g_Oh + i0) = hi;
        *(uint32_t*)(g_Ol + i0) = lo;
        split2h(O[ni][2] * inv1, O[ni][3] * inv1, hi, lo);
        size_t i1 = (size_t)(b * T + t1) * HD + col;
        *(uint32_t*)(g_Oh + i1) = hi;
        *(uint32_t*)(g_Ol + i1) = lo;
    }
}

// ---------------------------------------------------------------------------
extern "C" void kernel_launch(void* const* d_in, const int* in_sizes, int n_in,
                              void* d_out, int out_size)
{
    const float* x  = (const float*)d_in[0];
    const float* Wq = (const float*)d_in[1];
    const float* Wk = (const float*)d_in[2];
    const float* Wv = (const float*)d_in[3];
    const float* Wo = (const float*)d_in[4];
    const float* bo = (const float*)d_in[5];
    float* out = (float*)d_out;
    (void)in_sizes; (void)n_in; (void)out_size;

    cudaFuncSetAttribute(qkv_mma,     cudaFuncAttributeMaxDynamicSharedMemorySize, GEMM_SMEM);
    cudaFuncSetAttribute(outproj_mma, cudaFuncAttributeMaxDynamicSharedMemorySize, GEMM_SMEM);
    cudaFuncSetAttribute(attn_mma,    cudaFuncAttributeMaxDynamicSharedMemorySize, ATTN_SMEM);

    conv_all<<<8192, 256>>>(x, Wq, Wk, Wv, Wo);
    qkv_mma<<<dim3(M / 128, 24), 256, GEMM_SMEM>>>();
    attn_mma<<<dim3(T / 128, B * H), 256, ATTN_SMEM>>>();
    outproj_mma<<<dim3(M / 128, E / 128), 256, GEMM_SMEM>>>(bo, out);
}